// round 5
// baseline (speedup 1.0000x reference)
#include <cuda_runtime.h>

// Problem constants
#define NPG   61
#define NB    128          // batch (graphs)
#define NNODE 7808         // NB*NPG
#define NE    468480       // NB * 61*60
#define EPG   3660
#define LQ    160
#define NF    64
#define HC    128

// ---------------- device scratch (no allocations allowed) ----------------
__device__ float d_A[NB * 64 * 64];      // padded adjacency: A[g][d(64)][s(64)], zero pad & diag
__device__ float d_w1t[64 * 64 * 5];     // conv1 weights transposed: [(c*5+k)*64 + f]
__device__ float d_w2t[64 * 64 * 3];     // conv2 weights transposed: [(c*3+k)*64 + f]
__device__ float d_H0[NNODE * NF];       // conv output (N x 64)
__device__ float d_G1[NNODE * HC];       // gnn ping
__device__ float d_G2[NNODE * HC];       // gnn pong
__device__ float d_P[NPG * NB * HC];     // lin0 split-K partials: P[node][g][j]
__device__ float d_sc1[NF], d_sh1[NF];   // bn1 fused scale/shift
__device__ float d_sc2[HC], d_sh2[HC];   // bn2 fused scale/shift

// ---------------- K0: zero A, transpose conv weights ----------------
__global__ void k_prep(const float* __restrict__ w1, const float* __restrict__ w2) {
    int t0 = blockIdx.x * blockDim.x + threadIdx.x;
    int stride = gridDim.x * blockDim.x;
    for (int i = t0; i < NB * 64 * 64; i += stride) d_A[i] = 0.f;
    for (int i = t0; i < 64 * 64 * 5; i += stride) {
        int f = i & 63; int r = i >> 6; int k = r % 5; int c = r / 5;
        d_w1t[i] = w1[(f * 64 + c) * 5 + k];
    }
    for (int i = t0; i < 64 * 64 * 3; i += stride) {
        int f = i & 63; int r = i >> 6; int k = r % 3; int c = r / 3;
        d_w2t[i] = w2[(f * 64 + c) * 3 + k];
    }
}

// ---------------- K1: edge weights -> ew^T output block + adjacency ----------------
// edge_index arrives as int32 (harness dtype set is f32/i32/bf16).
__global__ void k_edges(const float* __restrict__ ef, const int* __restrict__ ei,
                        const float* __restrict__ eww, const float* __restrict__ ewb,
                        float* __restrict__ out) {
    int e = blockIdx.x * blockDim.x + threadIdx.x;
    if (e >= NE) return;
    float v = tanhf(fmaf(ef[e * 3 + 0], eww[0],
                   fmaf(ef[e * 3 + 1], eww[1],
                   fmaf(ef[e * 3 + 2], eww[2], ewb[0]))));
    int g = e / EPG;
    int i = e - g * EPG;
    out[NB * 4 + i * NB + g] = v;             // ew.reshape(NB, EPG).T, row-major (EPG x NB)
    int s = ei[e];
    int d = ei[NE + e];
    int g2 = d / NPG;
    int dl = d - g2 * NPG;
    int sl = s - g2 * NPG;
    d_A[(g2 * 64 + dl) * 64 + sl] = v;
}

// ---------------- K2: conv pipeline, one block per node, 64 threads ----------------
__global__ void __launch_bounds__(64) k_conv(
        const float* __restrict__ x,
        const float* __restrict__ w0, const float* __restrict__ b0,
        const float* __restrict__ b1, const float* __restrict__ b2) {
    int n = blockIdx.x;
    int f = threadIdx.x;                    // channel
    __shared__ float xs[LQ];
    __shared__ float p0s[64][27];           // p0 padded: index = t+2, t in [-2, 24]
    __shared__ float p1s[64][3];

    for (int i = f; i < LQ; i += 64) xs[i] = x[n * LQ + i];
    float w0r[7];
#pragma unroll
    for (int k = 0; k < 7; k++) w0r[k] = w0[f * 7 + k];
    float b0r = b0[f];
    __syncthreads();

    // conv0 (k=7, pad 0) + relu + maxpool7 -> p0[f][0..21]
#pragma unroll 1
    for (int j = 0; j < 22; j++) {
        float m = -1e30f;
#pragma unroll
        for (int u = 0; u < 7; u++) {
            int tp = 7 * j + u;
            float s = b0r;
#pragma unroll
            for (int k = 0; k < 7; k++) s = fmaf(xs[tp + k], w0r[k], s);
            m = fmaxf(m, s);
        }
        p0s[f][2 + j] = fmaxf(m, 0.f);
    }
    p0s[f][0] = 0.f; p0s[f][1] = 0.f;
    p0s[f][24] = 0.f; p0s[f][25] = 0.f; p0s[f][26] = 0.f;
    __syncthreads();

    // conv1 (k=5, pad 2): out[t] = b + sum_{c,k} p0[c][t+k-2] * w1[f][c][k]
    float acc[22];
    float b1r = b1[f];
#pragma unroll
    for (int t = 0; t < 22; t++) acc[t] = b1r;
#pragma unroll 1
    for (int c = 0; c < 64; c++) {
        float win[26];
#pragma unroll
        for (int t = 0; t < 26; t++) win[t] = p0s[c][t];
#pragma unroll
        for (int k = 0; k < 5; k++) {
            float wk = d_w1t[(c * 5 + k) * 64 + f];
#pragma unroll
            for (int t = 0; t < 22; t++) acc[t] = fmaf(win[t + k], wk, acc[t]);
        }
    }
    // relu + maxpool7 (truncates to 3 windows over t=0..20)
#pragma unroll
    for (int j = 0; j < 3; j++) {
        float m = acc[7 * j];
#pragma unroll
        for (int u = 1; u < 7; u++) m = fmaxf(m, acc[7 * j + u]);
        p1s[f][j] = fmaxf(m, 0.f);
    }
    __syncthreads();

    // conv2 (k=3, pad 0, len 3 -> 1)
    float s = b2[f];
#pragma unroll 1
    for (int c = 0; c < 64; c++) {
#pragma unroll
        for (int k = 0; k < 3; k++) s = fmaf(p1s[c][k], d_w2t[(c * 3 + k) * 64 + f], s);
    }
    d_H0[n * NF + f] = s;
}

// ---------------- BN stats (single block, 1024 threads) ----------------
__global__ void __launch_bounds__(1024) k_bnstats1(const float* __restrict__ gg,
                                                   const float* __restrict__ bb) {
    const int C = NF, NGRP = 1024 / NF;
    int t = threadIdx.x;
    int c = t & (C - 1);
    int grp = t >> 6;
    float s = 0.f, s2 = 0.f;
    for (int n = grp; n < NNODE; n += NGRP) {
        float v = d_H0[n * C + c];
        s += v; s2 += v * v;
    }
    __shared__ float ss[1024], ss2[1024];
    ss[t] = s; ss2[t] = s2;
    __syncthreads();
    if (t < C) {
        float a = 0.f, a2 = 0.f;
        for (int i = 0; i < NGRP; i++) { a += ss[i * C + c]; a2 += ss2[i * C + c]; }
        float mean = a / (float)NNODE;
        float var = a2 / (float)NNODE - mean * mean;
        float rs = rsqrtf(var + 1e-5f);
        d_sc1[c] = gg[c] * rs;
        d_sh1[c] = bb[c] - mean * gg[c] * rs;
    }
}

__global__ void __launch_bounds__(1024) k_bnstats2(const float* __restrict__ gg,
                                                   const float* __restrict__ bb) {
    const int C = HC, NGRP = 1024 / HC;
    int t = threadIdx.x;
    int c = t & (C - 1);
    int grp = t >> 7;
    float s = 0.f, s2 = 0.f;
    for (int n = grp; n < NNODE; n += NGRP) {
        float v = d_G1[n * C + c];
        s += v; s2 += v * v;
    }
    __shared__ float ss[1024], ss2[1024];
    ss[t] = s; ss2[t] = s2;
    __syncthreads();
    if (t < C) {
        float a = 0.f, a2 = 0.f;
        for (int i = 0; i < NGRP; i++) { a += ss[i * C + c]; a2 += ss2[i * C + c]; }
        float mean = a / (float)NNODE;
        float var = a2 / (float)NNODE - mean * mean;
        float rs = rsqrtf(var + 1e-5f);
        d_sc2[c] = gg[c] * rs;
        d_sh2[c] = bb[c] - mean * gg[c] * rs;
    }
}

// ---------------- GNN layer: block per graph, 128 threads ----------------
// h'_g(61 x 128) = A_g(61x61) @ (h_g @ W + b), optional relu / bn-on-input.
// INSEL/OUTSEL: 0 = d_H0, 1 = d_G1, 2 = d_G2
template<int K, bool BN, int INSEL, int OUTSEL>
__global__ void __launch_bounds__(128) k_gnn(const float* __restrict__ W,
                                             const float* __restrict__ bias,
                                             int do_relu) {
    const float* hin = (INSEL == 0) ? (const float*)d_H0
                     : (INSEL == 1) ? (const float*)d_G1 : (const float*)d_G2;
    float* hout = (OUTSEL == 1) ? (float*)d_G1 : (float*)d_G2;

    int g = blockIdx.x;
    int j = threadIdx.x;
    __shared__ float hs[61 * 128];          // phase1: input h (61 x K); phase2: hw (61 x 128)
    __shared__ float As[64 * 64];

    for (int idx = j; idx < 61 * K; idx += 128) {
        float v = hin[g * 61 * K + idx];
        if (BN) { int c = idx & (K - 1); v = fmaf(v, d_sc1[c], d_sh1[c]); }
        hs[idx] = v;
    }
    for (int idx = j; idx < 4096; idx += 128) As[idx] = d_A[g * 4096 + idx];
    __syncthreads();

    // hw[n] = b[j] + sum_k hs[n][k] * W[k][j]
    float hw[61];
    float bj = bias[j];
#pragma unroll
    for (int n = 0; n < 61; n++) hw[n] = bj;
    for (int k = 0; k < K; k++) {
        float wk = W[k * HC + j];
#pragma unroll
        for (int n = 0; n < 61; n++) hw[n] = fmaf(hs[n * K + k], wk, hw[n]);
    }
    __syncthreads();
    // store hw into hs (reused as hws[61][128])
#pragma unroll
    for (int n = 0; n < 61; n++) hs[n * HC + j] = hw[n];
    __syncthreads();

    // aggregate: h'[d][j] = sum_s A[d][s] * hws[s][j]
#pragma unroll 1
    for (int db = 0; db < 4; db++) {
        float acc[16];
#pragma unroll
        for (int t = 0; t < 16; t++) acc[t] = 0.f;
        for (int s = 0; s < 61; s++) {
            float v = hs[s * HC + j];
#pragma unroll
            for (int t = 0; t < 16; t++)
                acc[t] = fmaf(As[(db * 16 + t) * 64 + s], v, acc[t]);
        }
#pragma unroll
        for (int t = 0; t < 16; t++) {
            int d = db * 16 + t;
            if (d < 61) {
                float r = acc[t];
                if (do_relu) r = fmaxf(r, 0.f);
                hout[(g * 61 + d) * HC + j] = r;
            }
        }
    }
}

// ---------------- lin0: deterministic split-K over nodes ----------------
// grid (61, 8), 128 threads. Block (node, gchunk) computes partial
// P[node][g][j] = sum_ch bn2(h[g*61+node][ch]) * W0[(node*128+ch)*128 + j]
__global__ void __launch_bounds__(128) k_lin0(const float* __restrict__ W0) {
    int node = blockIdx.x;
    int gc = blockIdx.y;
    int j = threadIdx.x;
    __shared__ float vs[16][HC];
    for (int q = 0; q < 16; q++) {
        int g = gc * 16 + q;
        vs[q][j] = fmaf(d_G1[(g * 61 + node) * HC + j], d_sc2[j], d_sh2[j]);
    }
    __syncthreads();
    float acc[16];
#pragma unroll
    for (int q = 0; q < 16; q++) acc[q] = 0.f;
    for (int ch = 0; ch < HC; ch++) {
        float w = W0[(node * HC + ch) * HC + j];
#pragma unroll
        for (int q = 0; q < 16; q++) acc[q] = fmaf(vs[q][ch], w, acc[q]);
    }
#pragma unroll
    for (int q = 0; q < 16; q++) {
        int g = gc * 16 + q;
        d_P[(node * NB + g) * HC + j] = acc[q];
    }
}

// ---------------- head: reduce partials + lin1 + lin2 + log_softmax ----------------
__global__ void __launch_bounds__(128) k_head(const float* __restrict__ b0,
                                              const float* __restrict__ W1,
                                              const float* __restrict__ b1,
                                              const float* __restrict__ W2,
                                              const float* __restrict__ b2,
                                              float* __restrict__ out) {
    int g = blockIdx.x;
    int j = threadIdx.x;
    float z = b0[j];
    for (int node = 0; node < NPG; node++) z += d_P[(node * NB + g) * HC + j];
    z = fmaxf(z, 0.f);
    __shared__ float z1[HC];
    z1[j] = z;
    __syncthreads();
    float a = b1[j];
    for (int k = 0; k < HC; k++) a = fmaf(z1[k], W1[k * HC + j], a);
    a = fmaxf(a, 0.f);
    __shared__ float z2[HC];
    z2[j] = a;
    __syncthreads();
    __shared__ float z3[4];
    if (j < 4) {
        float s = b2[j];
        for (int k = 0; k < HC; k++) s = fmaf(z2[k], W2[k * 4 + j], s);
        z3[j] = s;
    }
    __syncthreads();
    if (j == 0) {
        float m = fmaxf(fmaxf(z3[0], z3[1]), fmaxf(z3[2], z3[3]));
        float se = 0.f;
        for (int i = 0; i < 4; i++) se += expf(z3[i] - m);
        float l = logf(se);
        for (int i = 0; i < 4; i++) out[g * 4 + i] = z3[i] - m - l;
    }
}

// ---------------- launch ----------------
extern "C" void kernel_launch(void* const* d_in, const int* in_sizes, int n_in,
                              void* d_out, int out_size) {
    const float* x    = (const float*)d_in[0];
    const int*   ei   = (const int*)d_in[1];    // edge_index as int32
    const float* ef   = (const float*)d_in[3];
    const float* cw0  = (const float*)d_in[4];
    const float* cb0  = (const float*)d_in[5];
    const float* cw1  = (const float*)d_in[6];
    const float* cb1  = (const float*)d_in[7];
    const float* cw2  = (const float*)d_in[8];
    const float* cb2  = (const float*)d_in[9];
    const float* bn1g = (const float*)d_in[10];
    const float* bn1b = (const float*)d_in[11];
    const float* gw0  = (const float*)d_in[12];
    const float* gb0  = (const float*)d_in[13];
    const float* gw1  = (const float*)d_in[14];
    const float* gb1  = (const float*)d_in[15];
    const float* gw2  = (const float*)d_in[16];
    const float* gb2  = (const float*)d_in[17];
    const float* bn2g = (const float*)d_in[18];
    const float* bn2b = (const float*)d_in[19];
    const float* lw0  = (const float*)d_in[20];
    const float* lb0  = (const float*)d_in[21];
    const float* lw1  = (const float*)d_in[22];
    const float* lb1  = (const float*)d_in[23];
    const float* lw2  = (const float*)d_in[24];
    const float* lb2  = (const float*)d_in[25];
    const float* eww  = (const float*)d_in[26];
    const float* ewb  = (const float*)d_in[27];
    float* out = (float*)d_out;

    k_prep<<<256, 256>>>(cw1, cw2);
    k_edges<<<(NE + 255) / 256, 256>>>(ef, ei, eww, ewb, out);
    k_conv<<<NNODE, 64>>>(x, cw0, cb0, cb1, cb2);
    k_bnstats1<<<1, 1024>>>(bn1g, bn1b);
    k_gnn<64, true, 0, 1><<<NB, 128>>>(gw0, gb0, 1);
    k_gnn<128, false, 1, 2><<<NB, 128>>>(gw1, gb1, 1);
    k_gnn<128, false, 2, 1><<<NB, 128>>>(gw2, gb2, 0);
    k_bnstats2<<<1, 1024>>>(bn2g, bn2b);
    dim3 lg(NPG, 8);
    k_lin0<<<lg, 128>>>(lw0);
    k_head<<<NB, 128>>>(lb0, lw1, lb1, lw2, lb2, out);
}

// round 6
// speedup vs baseline: 1.5951x; 1.5951x over previous
#include <cuda_runtime.h>

// Problem constants
#define NPG   61
#define NB    128
#define NNODE 7808         // NB*NPG
#define NE    468480       // NB * 61*60
#define EPG   3660
#define LQ    160
#define NF    64
#define HC    128

typedef unsigned long long ull;

// ---------------- f32x2 helpers ----------------
__device__ __forceinline__ ull pack2(float lo, float hi) {
    ull r; asm("mov.b64 %0, {%1, %2};" : "=l"(r) : "f"(lo), "f"(hi)); return r;
}
__device__ __forceinline__ float2 u2f(ull u) {
    float2 v; asm("mov.b64 {%0, %1}, %2;" : "=f"(v.x), "=f"(v.y) : "l"(u)); return v;
}
__device__ __forceinline__ ull fma2(ull a, ull b, ull c) {
    ull d; asm("fma.rn.f32x2 %0, %1, %2, %3;" : "=l"(d) : "l"(a), "l"(b), "l"(c)); return d;
}

// ---------------- device scratch ----------------
__device__ float  d_A[NB * 64 * 64];       // padded adjacency A[g][d][s]
__device__ float2 d_w1p[64 * 5 * 64];      // conv1 weights, dup-packed: [(c*5+k)*64+f] = (w,w)
__device__ float  d_w2t[64 * 3 * 64];      // conv2 weights transposed
__device__ float2 d_gw0p[32 * HC];         // gnn W0 k-pairs: [kp*HC+j] = (W[2kp][j], W[2kp+1][j])
__device__ float2 d_gw1p[64 * HC];
__device__ float2 d_gw2p[64 * HC];
__device__ float  d_H0[NNODE * NF];
__device__ float  d_G1[NNODE * HC];
__device__ float  d_G2[NNODE * HC];
__device__ float  d_P[NPG * NB * HC];
__device__ float  d_bp1s[61 * NF], d_bp1q[61 * NF];    // bn1 partials
__device__ float  d_bp2s[NB * HC], d_bp2q[NB * HC];    // bn2 partials (from gnn3)
__device__ float  d_sc1[NF], d_sh1[NF];
__device__ float  d_sc2[HC], d_sh2[HC];

// ---------------- K0: zero A, transpose/pack weights ----------------
__global__ void k_prep(const float* __restrict__ w1, const float* __restrict__ w2,
                       const float* __restrict__ gw0, const float* __restrict__ gw1,
                       const float* __restrict__ gw2) {
    int t0 = blockIdx.x * blockDim.x + threadIdx.x;
    int stride = gridDim.x * blockDim.x;
    for (int i = t0; i < NB * 64 * 64; i += stride) d_A[i] = 0.f;
    for (int i = t0; i < 64 * 5 * 64; i += stride) {
        int f = i & 63; int r = i >> 6; int k = r % 5; int c = r / 5;
        float v = w1[(f * 64 + c) * 5 + k];
        d_w1p[i] = make_float2(v, v);
    }
    for (int i = t0; i < 64 * 3 * 64; i += stride) {
        int f = i & 63; int r = i >> 6; int k = r % 3; int c = r / 3;
        d_w2t[i] = w2[(f * 64 + c) * 3 + k];
    }
    for (int i = t0; i < 32 * HC; i += stride) {
        int j = i & (HC - 1); int kp = i >> 7;
        d_gw0p[i] = make_float2(gw0[(2 * kp) * HC + j], gw0[(2 * kp + 1) * HC + j]);
    }
    for (int i = t0; i < 64 * HC; i += stride) {
        int j = i & (HC - 1); int kp = i >> 7;
        d_gw1p[i] = make_float2(gw1[(2 * kp) * HC + j], gw1[(2 * kp + 1) * HC + j]);
        d_gw2p[i] = make_float2(gw2[(2 * kp) * HC + j], gw2[(2 * kp + 1) * HC + j]);
    }
}

// ---------------- K1: edge weights -> ew^T output block + adjacency ----------------
__global__ void k_edges(const float* __restrict__ ef, const int* __restrict__ ei,
                        const float* __restrict__ eww, const float* __restrict__ ewb,
                        float* __restrict__ out) {
    int e = blockIdx.x * blockDim.x + threadIdx.x;
    if (e >= NE) return;
    float v = tanhf(fmaf(ef[e * 3 + 0], eww[0],
                   fmaf(ef[e * 3 + 1], eww[1],
                   fmaf(ef[e * 3 + 2], eww[2], ewb[0]))));
    int g = e / EPG;
    int i = e - g * EPG;
    out[NB * 4 + i * NB + g] = v;
    int s = ei[e];
    int d = ei[NE + e];
    int g2 = d / NPG;
    int dl = d - g2 * NPG;
    int sl = s - g2 * NPG;
    d_A[(g2 * 64 + dl) * 64 + sl] = v;
}

// ---------------- K2: conv pipeline, one block per node, 64 threads ----------------
__global__ void __launch_bounds__(64) k_conv(
        const float* __restrict__ x,
        const float* __restrict__ w0, const float* __restrict__ b0,
        const float* __restrict__ b1, const float* __restrict__ b2) {
    int n = blockIdx.x;
    int f = threadIdx.x;
    __shared__ float xs[LQ];
    __shared__ __align__(16) float p0s[64][30];   // padded: idx = t+2, valid 0..25, rows 8B-aligned
    __shared__ float p1s[64][3];

    for (int i = f; i < LQ; i += 64) xs[i] = x[n * LQ + i];
    float w0r[7];
#pragma unroll
    for (int k = 0; k < 7; k++) w0r[k] = w0[f * 7 + k];
    float b0r = b0[f];
    __syncthreads();

    // conv0 (k=7, pad 0) + relu + maxpool7
#pragma unroll 1
    for (int j = 0; j < 22; j++) {
        float m = -1e30f;
#pragma unroll
        for (int u = 0; u < 7; u++) {
            int tp = 7 * j + u;
            float s = b0r;
#pragma unroll
            for (int k = 0; k < 7; k++) s = fmaf(xs[tp + k], w0r[k], s);
            m = fmaxf(m, s);
        }
        p0s[f][2 + j] = fmaxf(m, 0.f);
    }
    p0s[f][0] = 0.f; p0s[f][1] = 0.f;
    p0s[f][24] = 0.f; p0s[f][25] = 0.f;
    __syncthreads();

    // conv1 (k=5, pad 2) with f32x2: pair j covers t = 2j, 2j+1 (11 pairs)
    float b1r = b1[f];
    ull acc2[11];
#pragma unroll
    for (int j = 0; j < 11; j++) acc2[j] = pack2(b1r, b1r);

#pragma unroll 1
    for (int c = 0; c < 64; c++) {
        const float2* row = reinterpret_cast<const float2*>(&p0s[c][0]);  // broadcast LDS.64
        float2 A[13];
#pragma unroll
        for (int m = 0; m < 13; m++) A[m] = row[m];
        ull a2[13], bB[12];
#pragma unroll
        for (int m = 0; m < 13; m++) a2[m] = pack2(A[m].x, A[m].y);
#pragma unroll
        for (int m = 0; m < 12; m++) bB[m] = pack2(A[m].y, A[m + 1].x);
        const float2* wp = &d_w1p[c * 5 * 64 + f];
        ull w0u = pack2(wp[0].x, wp[0].y);
        ull w1u = pack2(wp[64].x, wp[64].y);
        ull w2u = pack2(wp[128].x, wp[128].y);
        ull w3u = pack2(wp[192].x, wp[192].y);
        ull w4u = pack2(wp[256].x, wp[256].y);
#pragma unroll
        for (int j = 0; j < 11; j++) {
            acc2[j] = fma2(a2[j],     w0u, acc2[j]);
            acc2[j] = fma2(bB[j],     w1u, acc2[j]);
            acc2[j] = fma2(a2[j + 1], w2u, acc2[j]);
            acc2[j] = fma2(bB[j + 1], w3u, acc2[j]);
            acc2[j] = fma2(a2[j + 2], w4u, acc2[j]);
        }
    }
    float acc[22];
#pragma unroll
    for (int j = 0; j < 11; j++) {
        float2 v = u2f(acc2[j]);
        acc[2 * j] = v.x; acc[2 * j + 1] = v.y;
    }
    // relu + maxpool7 (3 windows)
#pragma unroll
    for (int j = 0; j < 3; j++) {
        float m = acc[7 * j];
#pragma unroll
        for (int u = 1; u < 7; u++) m = fmaxf(m, acc[7 * j + u]);
        p1s[f][j] = fmaxf(m, 0.f);
    }
    __syncthreads();

    // conv2 (k=3, pad 0, len 3 -> 1)
    float s = b2[f];
#pragma unroll 1
    for (int c = 0; c < 64; c++) {
#pragma unroll
        for (int k = 0; k < 3; k++) s = fmaf(p1s[c][k], d_w2t[(c * 3 + k) * 64 + f], s);
    }
    d_H0[n * NF + f] = s;
}

// ---------------- BN1 stats: parallel partials + finalize ----------------
__global__ void __launch_bounds__(256) k_bns1a() {
    int t = threadIdx.x;
    int c = t & 63;
    int grp = t >> 6;                       // 0..3
    int gid = blockIdx.x * 4 + grp;         // 0..243
    float s = 0.f, q = 0.f;
    for (int n = gid; n < NNODE; n += 244) {
        float v = d_H0[n * NF + c];
        s += v; q += v * v;
    }
    __shared__ float ss[256], sq[256];
    ss[t] = s; sq[t] = q;
    __syncthreads();
    if (t < 64) {
        float a = ss[t] + ss[64 + t] + ss[128 + t] + ss[192 + t];
        float b = sq[t] + sq[64 + t] + sq[128 + t] + sq[192 + t];
        d_bp1s[blockIdx.x * 64 + t] = a;
        d_bp1q[blockIdx.x * 64 + t] = b;
    }
}
__global__ void __launch_bounds__(64) k_bns1b(const float* __restrict__ gg,
                                              const float* __restrict__ bb) {
    int c = threadIdx.x;
    float s = 0.f, q = 0.f;
    for (int b = 0; b < 61; b++) { s += d_bp1s[b * 64 + c]; q += d_bp1q[b * 64 + c]; }
    float mean = s / (float)NNODE;
    float var = q / (float)NNODE - mean * mean;
    float rs = rsqrtf(var + 1e-5f);
    d_sc1[c] = gg[c] * rs;
    d_sh1[c] = bb[c] - mean * gg[c] * rs;
}

// ---------------- BN2 finalize (partials produced by gnn layer 3) ----------------
__global__ void __launch_bounds__(128) k_bns2b(const float* __restrict__ gg,
                                               const float* __restrict__ bb) {
    int c = threadIdx.x;
    float s = 0.f, q = 0.f;
    for (int g = 0; g < NB; g++) { s += d_bp2s[g * HC + c]; q += d_bp2q[g * HC + c]; }
    float mean = s / (float)NNODE;
    float var = q / (float)NNODE - mean * mean;
    float rs = rsqrtf(var + 1e-5f);
    d_sc2[c] = gg[c] * rs;
    d_sh2[c] = bb[c] - mean * gg[c] * rs;
}

// ---------------- GNN layer: block per graph, 128 threads ----------------
// h'_g(61 x 128) = A_g @ (bn?(h_g) @ W + b), relu optional; layer3 emits BN2 partial stats.
template<int K, bool BN, bool STATS, int INSEL, int OUTSEL, bool RELU, int WSEL>
__global__ void __launch_bounds__(128) k_gnn(const float* __restrict__ bias) {
    const float* hin = (INSEL == 0) ? (const float*)d_H0
                     : (INSEL == 1) ? (const float*)d_G1 : (const float*)d_G2;
    float* hout = (OUTSEL == 1) ? (float*)d_G1 : (float*)d_G2;
    const float2* Wp = (WSEL == 0) ? (const float2*)d_gw0p
                     : (WSEL == 1) ? (const float2*)d_gw1p : (const float2*)d_gw2p;

    int g = blockIdx.x;
    int j = threadIdx.x;
    __shared__ __align__(16) float hs[61 * HC];    // phase1: h (61 x K); phase2: hw (61 x 128)
    __shared__ __align__(16) float AsT[61 * 68];   // A transposed: AsT[s][d], padded stride 68

    for (int idx = j; idx < 61 * K; idx += 128) {
        float v = hin[g * 61 * K + idx];
        if (BN) { int c = idx & (K - 1); v = fmaf(v, d_sc1[c], d_sh1[c]); }
        hs[idx] = v;
    }
    for (int idx = j; idx < 4096; idx += 128) {
        int d = idx >> 6, s = idx & 63;
        float v = d_A[g * 4096 + idx];
        if (s < 61) AsT[s * 68 + d] = v;
    }
    __syncthreads();

    // hw[n] = b[j] + sum_k h[n][k] * W[k][j], f32x2 over k-pairs, n in two chunks
    float hw[61];
    {
        ull acc0[31];
#pragma unroll
        for (int n = 0; n < 31; n++) acc0[n] = 0ull;
#pragma unroll 1
        for (int kq = 0; kq < K / 4; kq++) {
            float2 wA = Wp[(2 * kq) * HC + j];
            float2 wB = Wp[(2 * kq + 1) * HC + j];
            ull ua = pack2(wA.x, wA.y), ub = pack2(wB.x, wB.y);
#pragma unroll
            for (int n = 0; n < 31; n++) {
                float4 h4 = *reinterpret_cast<const float4*>(&hs[n * K + 4 * kq]);
                acc0[n] = fma2(pack2(h4.x, h4.y), ua, acc0[n]);
                acc0[n] = fma2(pack2(h4.z, h4.w), ub, acc0[n]);
            }
        }
        float bj = bias[j];
#pragma unroll
        for (int n = 0; n < 31; n++) { float2 v = u2f(acc0[n]); hw[n] = bj + v.x + v.y; }
    }
    {
        ull acc1[30];
#pragma unroll
        for (int n = 0; n < 30; n++) acc1[n] = 0ull;
#pragma unroll 1
        for (int kq = 0; kq < K / 4; kq++) {
            float2 wA = Wp[(2 * kq) * HC + j];
            float2 wB = Wp[(2 * kq + 1) * HC + j];
            ull ua = pack2(wA.x, wA.y), ub = pack2(wB.x, wB.y);
#pragma unroll
            for (int n = 0; n < 30; n++) {
                float4 h4 = *reinterpret_cast<const float4*>(&hs[(n + 31) * K + 4 * kq]);
                acc1[n] = fma2(pack2(h4.x, h4.y), ua, acc1[n]);
                acc1[n] = fma2(pack2(h4.z, h4.w), ub, acc1[n]);
            }
        }
        float bj = bias[j];
#pragma unroll
        for (int n = 0; n < 30; n++) { float2 v = u2f(acc1[n]); hw[n + 31] = bj + v.x + v.y; }
    }
    __syncthreads();
#pragma unroll
    for (int n = 0; n < 61; n++) hs[n * HC + j] = hw[n];
    __syncthreads();

    // aggregate: h'[d][j] = sum_s A[d][s] * hw[s][j]; f32x2 over d-pairs
    ull acc2[32];
#pragma unroll
    for (int p = 0; p < 32; p++) acc2[p] = 0ull;
#pragma unroll 1
    for (int s = 0; s < 61; s++) {
        float v = hs[s * HC + j];
        ull v2 = pack2(v, v);
        const float4* arow = reinterpret_cast<const float4*>(&AsT[s * 68]);
#pragma unroll
        for (int t = 0; t < 16; t++) {
            float4 a4 = arow[t];            // broadcast LDS.128
            acc2[2 * t]     = fma2(pack2(a4.x, a4.y), v2, acc2[2 * t]);
            acc2[2 * t + 1] = fma2(pack2(a4.z, a4.w), v2, acc2[2 * t + 1]);
        }
    }
    float ssum = 0.f, sqsum = 0.f;
#pragma unroll
    for (int p = 0; p < 32; p++) {
        float2 r2 = u2f(acc2[p]);
        int d0 = 2 * p, d1 = 2 * p + 1;
        if (d0 < 61) {
            float r = r2.x;
            if (STATS) { ssum += r; sqsum += r * r; }
            if (RELU) r = fmaxf(r, 0.f);
            hout[(g * 61 + d0) * HC + j] = r;
        }
        if (d1 < 61) {
            float r = r2.y;
            if (STATS) { ssum += r; sqsum += r * r; }
            if (RELU) r = fmaxf(r, 0.f);
            hout[(g * 61 + d1) * HC + j] = r;
        }
    }
    if (STATS) {
        d_bp2s[g * HC + j] = ssum;
        d_bp2q[g * HC + j] = sqsum;
    }
}

// ---------------- lin0: deterministic split-K over nodes ----------------
__global__ void __launch_bounds__(128) k_lin0(const float* __restrict__ W0) {
    int node = blockIdx.x;
    int gc = blockIdx.y;
    int j = threadIdx.x;
    __shared__ float vs[16][HC];
    for (int q = 0; q < 16; q++) {
        int g = gc * 16 + q;
        vs[q][j] = fmaf(d_G1[(g * 61 + node) * HC + j], d_sc2[j], d_sh2[j]);
    }
    __syncthreads();
    float acc[16];
#pragma unroll
    for (int q = 0; q < 16; q++) acc[q] = 0.f;
#pragma unroll 1
    for (int ch = 0; ch < HC; ch++) {
        float w = W0[(node * HC + ch) * HC + j];
#pragma unroll
        for (int q = 0; q < 16; q++) acc[q] = fmaf(vs[q][ch], w, acc[q]);
    }
#pragma unroll
    for (int q = 0; q < 16; q++) {
        int g = gc * 16 + q;
        d_P[(node * NB + g) * HC + j] = acc[q];
    }
}

// ---------------- head ----------------
__global__ void __launch_bounds__(128) k_head(const float* __restrict__ b0,
                                              const float* __restrict__ W1,
                                              const float* __restrict__ b1,
                                              const float* __restrict__ W2,
                                              const float* __restrict__ b2,
                                              float* __restrict__ out) {
    int g = blockIdx.x;
    int j = threadIdx.x;
    float z = b0[j];
    for (int node = 0; node < NPG; node++) z += d_P[(node * NB + g) * HC + j];
    z = fmaxf(z, 0.f);
    __shared__ float z1[HC];
    z1[j] = z;
    __syncthreads();
    float a = b1[j];
    for (int k = 0; k < HC; k++) a = fmaf(z1[k], W1[k * HC + j], a);
    a = fmaxf(a, 0.f);
    __shared__ float z2[HC];
    z2[j] = a;
    __syncthreads();
    __shared__ float z3[4];
    if (j < 4) {
        float s = b2[j];
        for (int k = 0; k < HC; k++) s = fmaf(z2[k], W2[k * 4 + j], s);
        z3[j] = s;
    }
    __syncthreads();
    if (j == 0) {
        float m = fmaxf(fmaxf(z3[0], z3[1]), fmaxf(z3[2], z3[3]));
        float se = 0.f;
        for (int i = 0; i < 4; i++) se += expf(z3[i] - m);
        float l = logf(se);
        for (int i = 0; i < 4; i++) out[g * 4 + i] = z3[i] - m - l;
    }
}

// ---------------- launch ----------------
extern "C" void kernel_launch(void* const* d_in, const int* in_sizes, int n_in,
                              void* d_out, int out_size) {
    const float* x    = (const float*)d_in[0];
    const int*   ei   = (const int*)d_in[1];
    const float* ef   = (const float*)d_in[3];
    const float* cw0  = (const float*)d_in[4];
    const float* cb0  = (const float*)d_in[5];
    const float* cw1  = (const float*)d_in[6];
    const float* cb1  = (const float*)d_in[7];
    const float* cw2  = (const float*)d_in[8];
    const float* cb2  = (const float*)d_in[9];
    const float* bn1g = (const float*)d_in[10];
    const float* bn1b = (const float*)d_in[11];
    const float* gw0  = (const float*)d_in[12];
    const float* gb0  = (const float*)d_in[13];
    const float* gw1  = (const float*)d_in[14];
    const float* gb1  = (const float*)d_in[15];
    const float* gw2  = (const float*)d_in[16];
    const float* gb2  = (const float*)d_in[17];
    const float* bn2g = (const float*)d_in[18];
    const float* bn2b = (const float*)d_in[19];
    const float* lw0  = (const float*)d_in[20];
    const float* lb0  = (const float*)d_in[21];
    const float* lw1  = (const float*)d_in[22];
    const float* lb1  = (const float*)d_in[23];
    const float* lw2  = (const float*)d_in[24];
    const float* lb2  = (const float*)d_in[25];
    const float* eww  = (const float*)d_in[26];
    const float* ewb  = (const float*)d_in[27];
    float* out = (float*)d_out;

    k_prep<<<256, 256>>>(cw1, cw2, gw0, gw1, gw2);
    k_edges<<<(NE + 255) / 256, 256>>>(ef, ei, eww, ewb, out);
    k_conv<<<NNODE, 64>>>(x, cw0, cb0, cb1, cb2);
    k_bns1a<<<61, 256>>>();
    k_bns1b<<<1, 64>>>(bn1g, bn1b);
    k_gnn< 64, true,  false, 0, 1, true,  0><<<NB, 128>>>(gb0);
    k_gnn<128, false, false, 1, 2, true,  1><<<NB, 128>>>(gb1);
    k_gnn<128, false, true,  2, 1, false, 2><<<NB, 128>>>(gb2);
    k_bns2b<<<1, 128>>>(bn2g, bn2b);
    dim3 lg(NPG, 8);
    k_lin0<<<lg, 128>>>(lw0);
    k_head<<<NB, 128>>>(lb0, lw1, lb1, lw2, lb2, out);
}

// round 7
// speedup vs baseline: 1.6105x; 1.0097x over previous
#include <cuda_runtime.h>

// Problem constants
#define NPG   61
#define NB    128
#define NNODE 7808         // NB*NPG
#define NE    468480       // NB * 61*60
#define EPG   3660
#define LQ    160
#define NF    64
#define HC    128

typedef unsigned long long ull;

// ---------------- f32x2 helpers ----------------
__device__ __forceinline__ ull pack2(float lo, float hi) {
    ull r; asm("mov.b64 %0, {%1, %2};" : "=l"(r) : "f"(lo), "f"(hi)); return r;
}
__device__ __forceinline__ float2 u2f(ull u) {
    float2 v; asm("mov.b64 {%0, %1}, %2;" : "=f"(v.x), "=f"(v.y) : "l"(u)); return v;
}
__device__ __forceinline__ ull fma2(ull a, ull b, ull c) {
    ull d; asm("fma.rn.f32x2 %0, %1, %2, %3;" : "=l"(d) : "l"(a), "l"(b), "l"(c)); return d;
}

// ---------------- device scratch ----------------
__device__ float      d_At[NB * 64 * 64];     // TRANSPOSED adjacency At[g][s][d]
__device__ ull        d_w1u[64 * 5 * 64];     // conv1 weights dup-packed as ull
__device__ float      d_w2t[64 * 3 * 64];     // conv2 weights transposed
__device__ ulonglong2 d_gw0u[16 * HC];        // gnn W0: [kq*HC+j] = {(W[4kq],W[4kq+1]), (W[4kq+2],W[4kq+3])}
__device__ ulonglong2 d_gw1u[32 * HC];
__device__ ulonglong2 d_gw2u[32 * HC];
__device__ float      d_H0[NNODE * NF];
__device__ float      d_G1[NNODE * HC];
__device__ float      d_G2[NNODE * HC];
__device__ float      d_HW[NNODE * HC];       // per-layer h@W staging
__device__ float      d_P[NPG * NB * HC];
__device__ float      d_bp1s[61 * NF], d_bp1q[61 * NF];
__device__ float      d_bp2s[2 * NB * HC], d_bp2q[2 * NB * HC];
__device__ float      d_sc1[NF], d_sh1[NF];
__device__ float      d_sc2[HC], d_sh2[HC];

// ---------------- K0: zero At, transpose/pack weights ----------------
__global__ void k_prep(const float* __restrict__ w1, const float* __restrict__ w2,
                       const float* __restrict__ gw0, const float* __restrict__ gw1,
                       const float* __restrict__ gw2) {
    int t0 = blockIdx.x * blockDim.x + threadIdx.x;
    int stride = gridDim.x * blockDim.x;
    for (int i = t0; i < NB * 64 * 64; i += stride) d_At[i] = 0.f;
    for (int i = t0; i < 64 * 5 * 64; i += stride) {
        int f = i & 63; int r = i >> 6; int k = r % 5; int c = r / 5;
        float v = w1[(f * 64 + c) * 5 + k];
        d_w1u[i] = pack2(v, v);
    }
    for (int i = t0; i < 64 * 3 * 64; i += stride) {
        int f = i & 63; int r = i >> 6; int k = r % 3; int c = r / 3;
        d_w2t[i] = w2[(f * 64 + c) * 3 + k];
    }
    for (int i = t0; i < 16 * HC; i += stride) {
        int j = i & (HC - 1); int kq = i >> 7;
        ulonglong2 u;
        u.x = pack2(gw0[(4 * kq) * HC + j], gw0[(4 * kq + 1) * HC + j]);
        u.y = pack2(gw0[(4 * kq + 2) * HC + j], gw0[(4 * kq + 3) * HC + j]);
        d_gw0u[i] = u;
    }
    for (int i = t0; i < 32 * HC; i += stride) {
        int j = i & (HC - 1); int kq = i >> 7;
        ulonglong2 u, v;
        u.x = pack2(gw1[(4 * kq) * HC + j], gw1[(4 * kq + 1) * HC + j]);
        u.y = pack2(gw1[(4 * kq + 2) * HC + j], gw1[(4 * kq + 3) * HC + j]);
        d_gw1u[i] = u;
        v.x = pack2(gw2[(4 * kq) * HC + j], gw2[(4 * kq + 1) * HC + j]);
        v.y = pack2(gw2[(4 * kq + 2) * HC + j], gw2[(4 * kq + 3) * HC + j]);
        d_gw2u[i] = v;
    }
}

// ---------------- K1: edges. grid (115, 4), block 1024 ----------------
// warp w handles graph g0+w, lanes cover 32 consecutive i. smem transpose for
// coalesced ew^T stores; d_At[g][s][d] stores are naturally coalesced.
__global__ void __launch_bounds__(1024) k_edges(
        const float* __restrict__ ef, const int* __restrict__ ei,
        const float* __restrict__ eww, const float* __restrict__ ewb,
        float* __restrict__ out) {
    int w = threadIdx.x >> 5;
    int l = threadIdx.x & 31;
    int i0 = blockIdx.x * 32;
    int g0 = blockIdx.y * 32;
    __shared__ float ts[32][33];

    int g = g0 + w;
    int i = i0 + l;
    float v = 0.f;
    if (i < EPG) {
        int e = g * EPG + i;
        v = tanhf(fmaf(ef[e * 3 + 0], eww[0],
                 fmaf(ef[e * 3 + 1], eww[1],
                 fmaf(ef[e * 3 + 2], eww[2], ewb[0]))));
        int s = ei[e];
        int d = ei[NE + e];
        int g2 = d / NPG;
        int dl = d - g2 * NPG;
        int sl = s - g2 * NPG;
        d_At[(g2 * 64 + sl) * 64 + dl] = v;   // transposed, coalesced over dl
    }
    ts[w][l] = v;
    __syncthreads();
    int iw = i0 + w;
    if (iw < EPG) out[NB * 4 + iw * NB + g0 + l] = ts[l][w];   // coalesced 128B
}

// ---------------- K2: conv pipeline, one block per node, 64 threads ----------------
__global__ void __launch_bounds__(64) k_conv(
        const float* __restrict__ x,
        const float* __restrict__ w0, const float* __restrict__ b0,
        const float* __restrict__ b1, const float* __restrict__ b2) {
    int n = blockIdx.x;
    int f = threadIdx.x;
    __shared__ __align__(16) float xs[LQ];
    __shared__ __align__(16) float p0s[64][30];   // idx = t+2, valid 0..25
    __shared__ float p1s[64][3];

    for (int i = f; i < LQ; i += 64) xs[i] = x[n * LQ + i];
    float w0r[7];
#pragma unroll
    for (int k = 0; k < 7; k++) w0r[k] = w0[f * 7 + k];
    ull w0d[7];
#pragma unroll
    for (int k = 0; k < 7; k++) w0d[k] = pack2(w0r[k], w0r[k]);
    float b0r = b0[f];
    ull b0d = pack2(b0r, b0r);
    __syncthreads();

    // conv0 (k=7) + relu + maxpool7, f32x2 packed over window pairs (2jp, 2jp+1)
#pragma unroll 1
    for (int jp = 0; jp < 11; jp++) {
        const float2* xr = reinterpret_cast<const float2*>(&xs[14 * jp]);
        float a[20];
#pragma unroll
        for (int m = 0; m < 10; m++) { float2 t = xr[m]; a[2 * m] = t.x; a[2 * m + 1] = t.y; }
        ull xq[13];
#pragma unroll
        for (int l = 0; l < 13; l++) xq[l] = pack2(a[l], a[l + 7]);
        ull s[7];
#pragma unroll
        for (int u = 0; u < 7; u++) s[u] = b0d;
#pragma unroll
        for (int k = 0; k < 7; k++)
#pragma unroll
            for (int u = 0; u < 7; u++) s[u] = fma2(xq[u + k], w0d[k], s[u]);
        float m0 = -1e30f, m1 = -1e30f;
#pragma unroll
        for (int u = 0; u < 7; u++) {
            float2 v = u2f(s[u]);
            m0 = fmaxf(m0, v.x); m1 = fmaxf(m1, v.y);
        }
        p0s[f][2 + 2 * jp] = fmaxf(m0, 0.f);
        p0s[f][2 + 2 * jp + 1] = fmaxf(m1, 0.f);
    }
    p0s[f][0] = 0.f; p0s[f][1] = 0.f;
    p0s[f][24] = 0.f; p0s[f][25] = 0.f;
    __syncthreads();

    // conv1 (k=5, pad 2), f32x2 over t-pairs
    float b1r = b1[f];
    ull acc2[11];
#pragma unroll
    for (int j = 0; j < 11; j++) acc2[j] = pack2(b1r, b1r);

#pragma unroll 1
    for (int c = 0; c < 64; c++) {
        const float2* row = reinterpret_cast<const float2*>(&p0s[c][0]);
        float2 A[13];
#pragma unroll
        for (int m = 0; m < 13; m++) A[m] = row[m];
        ull a2[13], bB[12];
#pragma unroll
        for (int m = 0; m < 13; m++) a2[m] = pack2(A[m].x, A[m].y);
#pragma unroll
        for (int m = 0; m < 12; m++) bB[m] = pack2(A[m].y, A[m + 1].x);
        const ull* wp = &d_w1u[c * 5 * 64 + f];
        ull w0u = wp[0], w1u = wp[64], w2u = wp[128], w3u = wp[192], w4u = wp[256];
#pragma unroll
        for (int j = 0; j < 11; j++) {
            acc2[j] = fma2(a2[j],     w0u, acc2[j]);
            acc2[j] = fma2(bB[j],     w1u, acc2[j]);
            acc2[j] = fma2(a2[j + 1], w2u, acc2[j]);
            acc2[j] = fma2(bB[j + 1], w3u, acc2[j]);
            acc2[j] = fma2(a2[j + 2], w4u, acc2[j]);
        }
    }
    float acc[22];
#pragma unroll
    for (int j = 0; j < 11; j++) {
        float2 v = u2f(acc2[j]);
        acc[2 * j] = v.x; acc[2 * j + 1] = v.y;
    }
#pragma unroll
    for (int j = 0; j < 3; j++) {
        float m = acc[7 * j];
#pragma unroll
        for (int u = 1; u < 7; u++) m = fmaxf(m, acc[7 * j + u]);
        p1s[f][j] = fmaxf(m, 0.f);
    }
    __syncthreads();

    // conv2 (k=3, len 3 -> 1)
    float s = b2[f];
#pragma unroll 1
    for (int c = 0; c < 64; c++) {
#pragma unroll
        for (int k = 0; k < 3; k++) s = fmaf(p1s[c][k], d_w2t[(c * 3 + k) * 64 + f], s);
    }
    d_H0[n * NF + f] = s;
}

// ---------------- BN1 stats ----------------
__global__ void __launch_bounds__(256) k_bns1a() {
    int t = threadIdx.x;
    int c = t & 63;
    int grp = t >> 6;
    int gid = blockIdx.x * 4 + grp;
    float s = 0.f, q = 0.f;
    for (int n = gid; n < NNODE; n += 244) {
        float v = d_H0[n * NF + c];
        s += v; q += v * v;
    }
    __shared__ float ss[256], sq[256];
    ss[t] = s; sq[t] = q;
    __syncthreads();
    if (t < 64) {
        d_bp1s[blockIdx.x * 64 + t] = ss[t] + ss[64 + t] + ss[128 + t] + ss[192 + t];
        d_bp1q[blockIdx.x * 64 + t] = sq[t] + sq[64 + t] + sq[128 + t] + sq[192 + t];
    }
}
__global__ void __launch_bounds__(64) k_bns1b(const float* __restrict__ gg,
                                              const float* __restrict__ bb) {
    int c = threadIdx.x;
    float s = 0.f, q = 0.f;
    for (int b = 0; b < 61; b++) { s += d_bp1s[b * 64 + c]; q += d_bp1q[b * 64 + c]; }
    float mean = s / (float)NNODE;
    float var = q / (float)NNODE - mean * mean;
    float rs = rsqrtf(var + 1e-5f);
    d_sc1[c] = gg[c] * rs;
    d_sh1[c] = bb[c] - mean * gg[c] * rs;
}
__global__ void __launch_bounds__(128) k_bns2b(const float* __restrict__ gg,
                                               const float* __restrict__ bb) {
    int c = threadIdx.x;
    float s = 0.f, q = 0.f;
    for (int g = 0; g < 2 * NB; g++) { s += d_bp2s[g * HC + c]; q += d_bp2q[g * HC + c]; }
    float mean = s / (float)NNODE;
    float var = q / (float)NNODE - mean * mean;
    float rs = rsqrtf(var + 1e-5f);
    d_sc2[c] = gg[c] * rs;
    d_sh2[c] = bb[c] - mean * gg[c] * rs;
}

// ---------------- GNN phase A: hw = bn?(h) @ W + b. grid (NB, 2), 128 thr ----------------
template<int K, bool BN, int INSEL, int WSEL>
__global__ void __launch_bounds__(128) k_gnn_a(const float* __restrict__ bias) {
    const float* hin = (INSEL == 0) ? (const float*)d_H0
                     : (INSEL == 1) ? (const float*)d_G1 : (const float*)d_G2;
    const ulonglong2* Wu = (WSEL == 0) ? (const ulonglong2*)d_gw0u
                         : (WSEL == 1) ? (const ulonglong2*)d_gw1u : (const ulonglong2*)d_gw2u;
    int g = blockIdx.x;
    int half = blockIdx.y;
    int n0 = half ? 31 : 0;
    int NR = half ? 30 : 31;
    int j = threadIdx.x;
    __shared__ __align__(16) float hs[31 * K];

    for (int idx = j; idx < NR * K; idx += 128) {
        float v = hin[(g * 61 + n0) * K + idx];
        if (BN) { int c = idx & (K - 1); v = fmaf(v, d_sc1[c], d_sh1[c]); }
        hs[idx] = v;
    }
    __syncthreads();

    ull acc[31];
#pragma unroll
    for (int n = 0; n < 31; n++) acc[n] = 0ull;
#pragma unroll 1
    for (int kq = 0; kq < K / 4; kq++) {
        ulonglong2 w = Wu[kq * HC + j];
#pragma unroll
        for (int n = 0; n < 31; n++) {
            if (n < ((K == 64) ? 31 : 31)) {   // full unroll hint
                ulonglong2 h2 = *reinterpret_cast<const ulonglong2*>(&hs[n * K + 4 * kq]);
                acc[n] = fma2(h2.x, w.x, acc[n]);
                acc[n] = fma2(h2.y, w.y, acc[n]);
            }
        }
    }
    float bj = bias[j];
    for (int n = 0; n < NR; n++) {
        float2 v = u2f(acc[n]);
        d_HW[(g * 61 + n0 + n) * HC + j] = bj + v.x + v.y;
    }
}

// ---------------- GNN phase B: h' = A @ hw (+relu/+stats). grid (NB, 2), 128 thr ----------------
template<bool RELU, bool STATS, int OUTSEL>
__global__ void __launch_bounds__(128) k_gnn_b() {
    float* hout = (OUTSEL == 1) ? (float*)d_G1 : (float*)d_G2;
    int g = blockIdx.x;
    int half = blockIdx.y;
    int doff = half * 32;
    int ND = half ? 29 : 32;                 // d range: 0..31 / 32..60
    int j = threadIdx.x;
    __shared__ __align__(16) float hs[61 * HC];
    __shared__ __align__(16) float As2[61 * 36];

    for (int idx = j; idx < 61 * HC; idx += 128) hs[idx] = d_HW[g * 61 * HC + idx];
    for (int idx = j; idx < 61 * 32; idx += 128) {
        int s = idx >> 5, dd = idx & 31;
        As2[s * 36 + dd] = d_At[g * 4096 + s * 64 + doff + dd];
    }
    __syncthreads();

    ull acc[16];
#pragma unroll
    for (int p = 0; p < 16; p++) acc[p] = 0ull;
#pragma unroll 1
    for (int s = 0; s < 61; s++) {
        float v = hs[s * HC + j];
        ull v2 = pack2(v, v);
        const ulonglong2* ar = reinterpret_cast<const ulonglong2*>(&As2[s * 36]);
#pragma unroll
        for (int p = 0; p < 8; p++) {
            ulonglong2 a = ar[p];
            acc[2 * p]     = fma2(a.x, v2, acc[2 * p]);
            acc[2 * p + 1] = fma2(a.y, v2, acc[2 * p + 1]);
        }
    }
    float ssum = 0.f, sqsum = 0.f;
#pragma unroll
    for (int p = 0; p < 16; p++) {
        float2 r2 = u2f(acc[p]);
        int d0 = 2 * p, d1 = 2 * p + 1;
        if (d0 < ND) {
            float r = r2.x;
            if (STATS) { ssum += r; sqsum += r * r; }
            if (RELU) r = fmaxf(r, 0.f);
            hout[(g * 61 + doff + d0) * HC + j] = r;
        }
        if (d1 < ND) {
            float r = r2.y;
            if (STATS) { ssum += r; sqsum += r * r; }
            if (RELU) r = fmaxf(r, 0.f);
            hout[(g * 61 + doff + d1) * HC + j] = r;
        }
    }
    if (STATS) {
        d_bp2s[(g * 2 + half) * HC + j] = ssum;
        d_bp2q[(g * 2 + half) * HC + j] = sqsum;
    }
}

// ---------------- lin0: split-K over nodes, f32x2. grid (61, 8), 128 thr ----------------
__global__ void __launch_bounds__(128) k_lin0(const float* __restrict__ W0) {
    int node = blockIdx.x;
    int gc = blockIdx.y;
    int j = threadIdx.x;
    __shared__ __align__(16) float vsT[HC * 20];   // vsT[ch][q], stride 20
    float sc = d_sc2[j], sh = d_sh2[j];
#pragma unroll 1
    for (int q = 0; q < 16; q++) {
        int g = gc * 16 + q;
        vsT[j * 20 + q] = fmaf(d_G1[(g * 61 + node) * HC + j], sc, sh);
    }
    __syncthreads();
    ull acc[8];
#pragma unroll
    for (int p = 0; p < 8; p++) acc[p] = 0ull;
#pragma unroll 1
    for (int ch = 0; ch < HC; ch++) {
        float w = W0[(node * HC + ch) * HC + j];
        ull wd = pack2(w, w);
        const ulonglong2* vr = reinterpret_cast<const ulonglong2*>(&vsT[ch * 20]);
#pragma unroll
        for (int p = 0; p < 4; p++) {
            ulonglong2 v = vr[p];
            acc[2 * p]     = fma2(v.x, wd, acc[2 * p]);
            acc[2 * p + 1] = fma2(v.y, wd, acc[2 * p + 1]);
        }
    }
#pragma unroll
    for (int p = 0; p < 8; p++) {
        float2 v = u2f(acc[p]);
        int g0 = gc * 16 + 2 * p;
        d_P[(node * NB + g0) * HC + j] = v.x;
        d_P[(node * NB + g0 + 1) * HC + j] = v.y;
    }
}

// ---------------- head ----------------
__global__ void __launch_bounds__(128) k_head(const float* __restrict__ b0,
                                              const float* __restrict__ W1,
                                              const float* __restrict__ b1,
                                              const float* __restrict__ W2,
                                              const float* __restrict__ b2,
                                              float* __restrict__ out) {
    int g = blockIdx.x;
    int j = threadIdx.x;
    float z = b0[j];
    for (int node = 0; node < NPG; node++) z += d_P[(node * NB + g) * HC + j];
    z = fmaxf(z, 0.f);
    __shared__ float z1[HC];
    z1[j] = z;
    __syncthreads();
    float a = b1[j];
    for (int k = 0; k < HC; k++) a = fmaf(z1[k], W1[k * HC + j], a);
    a = fmaxf(a, 0.f);
    __shared__ float z2[HC];
    z2[j] = a;
    __syncthreads();
    __shared__ float z3[4];
    if (j < 4) {
        float s = b2[j];
        for (int k = 0; k < HC; k++) s = fmaf(z2[k], W2[k * 4 + j], s);
        z3[j] = s;
    }
    __syncthreads();
    if (j == 0) {
        float m = fmaxf(fmaxf(z3[0], z3[1]), fmaxf(z3[2], z3[3]));
        float se = 0.f;
        for (int i = 0; i < 4; i++) se += expf(z3[i] - m);
        float l = logf(se);
        for (int i = 0; i < 4; i++) out[g * 4 + i] = z3[i] - m - l;
    }
}

// ---------------- launch ----------------
extern "C" void kernel_launch(void* const* d_in, const int* in_sizes, int n_in,
                              void* d_out, int out_size) {
    const float* x    = (const float*)d_in[0];
    const int*   ei   = (const int*)d_in[1];
    const float* ef   = (const float*)d_in[3];
    const float* cw0  = (const float*)d_in[4];
    const float* cb0  = (const float*)d_in[5];
    const float* cw1  = (const float*)d_in[6];
    const float* cb1  = (const float*)d_in[7];
    const float* cw2  = (const float*)d_in[8];
    const float* cb2  = (const float*)d_in[9];
    const float* bn1g = (const float*)d_in[10];
    const float* bn1b = (const float*)d_in[11];
    const float* gb0  = (const float*)d_in[13];
    const float* gb1  = (const float*)d_in[15];
    const float* gb2  = (const float*)d_in[17];
    const float* bn2g = (const float*)d_in[18];
    const float* bn2b = (const float*)d_in[19];
    const float* lw0  = (const float*)d_in[20];
    const float* lb0  = (const float*)d_in[21];
    const float* lw1  = (const float*)d_in[22];
    const float* lb1  = (const float*)d_in[23];
    const float* lw2  = (const float*)d_in[24];
    const float* lb2  = (const float*)d_in[25];
    const float* eww  = (const float*)d_in[26];
    const float* ewb  = (const float*)d_in[27];
    const float* gw0  = (const float*)d_in[12];
    const float* gw1  = (const float*)d_in[14];
    const float* gw2  = (const float*)d_in[16];
    float* out = (float*)d_out;

    k_prep<<<256, 256>>>(cw1, cw2, gw0, gw1, gw2);
    dim3 eg((EPG + 31) / 32, NB / 32);
    k_edges<<<eg, 1024>>>(ef, ei, eww, ewb, out);
    k_conv<<<NNODE, 64>>>(x, cw0, cb0, cb1, cb2);
    k_bns1a<<<61, 256>>>();
    k_bns1b<<<1, 64>>>(bn1g, bn1b);
    dim3 gg(NB, 2);
    k_gnn_a< 64, true,  0, 0><<<gg, 128>>>(gb0);
    k_gnn_b<true,  false, 1><<<gg, 128>>>();
    k_gnn_a<128, false, 1, 1><<<gg, 128>>>(gb1);
    k_gnn_b<true,  false, 2><<<gg, 128>>>();
    k_gnn_a<128, false, 2, 2><<<gg, 128>>>(gb2);
    k_gnn_b<false, true,  1><<<gg, 128>>>();
    k_bns2b<<<1, 128>>>(bn2g, bn2b);
    dim3 lg(NPG, 8);
    k_lin0<<<lg, 128>>>(lw0);
    k_head<<<NB, 128>>>(lb0, lw1, lb1, lw2, lb2, out);
}

// round 8
// speedup vs baseline: 1.6733x; 1.0390x over previous
#include <cuda_runtime.h>

// Problem constants
#define NPG   61
#define NB    128
#define NNODE 7808         // NB*NPG
#define NE    468480       // NB * 61*60
#define EPG   3660
#define LQ    160
#define NF    64
#define HC    128

typedef unsigned long long ull;

// ---------------- f32x2 helpers ----------------
__device__ __forceinline__ ull pack2(float lo, float hi) {
    ull r; asm("mov.b64 %0, {%1, %2};" : "=l"(r) : "f"(lo), "f"(hi)); return r;
}
__device__ __forceinline__ float2 u2f(ull u) {
    float2 v; asm("mov.b64 {%0, %1}, %2;" : "=f"(v.x), "=f"(v.y) : "l"(u)); return v;
}
__device__ __forceinline__ ull fma2(ull a, ull b, ull c) {
    ull d; asm("fma.rn.f32x2 %0, %1, %2, %3;" : "=l"(d) : "l"(a), "l"(b), "l"(c)); return d;
}

// ---------------- device scratch ----------------
__device__ float      d_At[NB * 64 * 64];     // TRANSPOSED adjacency At[g][s][d]
__device__ ull        d_w1u[64 * 5 * 64];     // conv1 weights dup-packed as ull
__device__ float      d_w2t[64 * 3 * 64];     // conv2 weights transposed
__device__ ulonglong2 d_gw0u[16 * HC];
__device__ ulonglong2 d_gw1u[32 * HC];
__device__ ulonglong2 d_gw2u[32 * HC];
__device__ float      d_H0[NNODE * NF];
__device__ float      d_G1[NNODE * HC];
__device__ float      d_G2[NNODE * HC];
__device__ float      d_HW[NNODE * HC];
__device__ float      d_P[NB * NPG * HC];     // lin0 partials, [g][node][j]
__device__ float      d_bp1s[61 * NF], d_bp1q[61 * NF];
__device__ float      d_bp2s[2 * NB * HC], d_bp2q[2 * NB * HC];
__device__ float      d_sc1[NF], d_sh1[NF];
__device__ float      d_sc2[HC], d_sh2[HC];

// ---------------- K0: zero At, transpose/pack weights ----------------
__global__ void k_prep(const float* __restrict__ w1, const float* __restrict__ w2,
                       const float* __restrict__ gw0, const float* __restrict__ gw1,
                       const float* __restrict__ gw2) {
    int t0 = blockIdx.x * blockDim.x + threadIdx.x;
    int stride = gridDim.x * blockDim.x;
    for (int i = t0; i < NB * 64 * 64; i += stride) d_At[i] = 0.f;
    for (int i = t0; i < 64 * 5 * 64; i += stride) {
        int f = i & 63; int r = i >> 6; int k = r % 5; int c = r / 5;
        float v = w1[(f * 64 + c) * 5 + k];
        d_w1u[i] = pack2(v, v);
    }
    for (int i = t0; i < 64 * 3 * 64; i += stride) {
        int f = i & 63; int r = i >> 6; int k = r % 3; int c = r / 3;
        d_w2t[i] = w2[(f * 64 + c) * 3 + k];
    }
    for (int i = t0; i < 16 * HC; i += stride) {
        int j = i & (HC - 1); int kq = i >> 7;
        ulonglong2 u;
        u.x = pack2(gw0[(4 * kq) * HC + j], gw0[(4 * kq + 1) * HC + j]);
        u.y = pack2(gw0[(4 * kq + 2) * HC + j], gw0[(4 * kq + 3) * HC + j]);
        d_gw0u[i] = u;
    }
    for (int i = t0; i < 32 * HC; i += stride) {
        int j = i & (HC - 1); int kq = i >> 7;
        ulonglong2 u, v;
        u.x = pack2(gw1[(4 * kq) * HC + j], gw1[(4 * kq + 1) * HC + j]);
        u.y = pack2(gw1[(4 * kq + 2) * HC + j], gw1[(4 * kq + 3) * HC + j]);
        d_gw1u[i] = u;
        v.x = pack2(gw2[(4 * kq) * HC + j], gw2[(4 * kq + 1) * HC + j]);
        v.y = pack2(gw2[(4 * kq + 2) * HC + j], gw2[(4 * kq + 3) * HC + j]);
        d_gw2u[i] = v;
    }
}

// ---------------- K1: edges ----------------
__global__ void __launch_bounds__(1024) k_edges(
        const float* __restrict__ ef, const int* __restrict__ ei,
        const float* __restrict__ eww, const float* __restrict__ ewb,
        float* __restrict__ out) {
    int w = threadIdx.x >> 5;
    int l = threadIdx.x & 31;
    int i0 = blockIdx.x * 32;
    int g0 = blockIdx.y * 32;
    __shared__ float ts[32][33];

    int g = g0 + w;
    int i = i0 + l;
    float v = 0.f;
    if (i < EPG) {
        int e = g * EPG + i;
        v = tanhf(fmaf(ef[e * 3 + 0], eww[0],
                 fmaf(ef[e * 3 + 1], eww[1],
                 fmaf(ef[e * 3 + 2], eww[2], ewb[0]))));
        int s = ei[e];
        int d = ei[NE + e];
        int g2 = d / NPG;
        int dl = d - g2 * NPG;
        int sl = s - g2 * NPG;
        d_At[(g2 * 64 + sl) * 64 + dl] = v;
    }
    ts[w][l] = v;
    __syncthreads();
    int iw = i0 + w;
    if (iw < EPG) out[NB * 4 + iw * NB + g0 + l] = ts[l][w];
}

// ---------------- K2: conv pipeline, one block per node, 64 threads ----------------
// conv1 reads the pooled conv0 output from TWO pre-paired smem layouts:
//   pe[f][m] = (P[2m-2], P[2m-1])  m=0..12   (taps k=0,2,4 at pe[j],pe[j+1],pe[j+2])
//   po[f][m] = (P[2m-1], P[2m])    m=0..11   (taps k=1,3 at po[j],po[j+1])
// so the inner loop is pure LDS.64 + FFMA2 with no register repacking.
__global__ void __launch_bounds__(64) k_conv(
        const float* __restrict__ x,
        const float* __restrict__ w0, const float* __restrict__ b0,
        const float* __restrict__ b1, const float* __restrict__ b2) {
    int n = blockIdx.x;
    int f = threadIdx.x;
    __shared__ __align__(16) float xs[LQ];
    __shared__ __align__(16) ull   pes[64][13];
    __shared__ __align__(16) float pof[64][24];   // read as ull pairs: po[m] = (pof[2m], pof[2m+1])
    __shared__ float p1s[64][3];

    for (int i = f; i < LQ; i += 64) xs[i] = x[n * LQ + i];
    float w0r[7];
#pragma unroll
    for (int k = 0; k < 7; k++) w0r[k] = w0[f * 7 + k];
    ull w0d[7];
#pragma unroll
    for (int k = 0; k < 7; k++) w0d[k] = pack2(w0r[k], w0r[k]);
    float b0r = b0[f];
    ull b0d = pack2(b0r, b0r);
    // border zeros
    pes[f][0] = 0ull;            // (P[-2], P[-1])
    pes[f][12] = 0ull;           // (P[22], P[23])
    pof[f][0] = 0.f;             // P[-1]
    pof[f][23] = 0.f;            // P[22]
    __syncthreads();

    // conv0 (k=7) + relu + maxpool7; window-pair f32x2 (outputs t=2jp, 2jp+1)
#pragma unroll 1
    for (int jp = 0; jp < 11; jp++) {
        const float2* xr = reinterpret_cast<const float2*>(&xs[14 * jp]);
        float a[20];
#pragma unroll
        for (int m = 0; m < 10; m++) { float2 t = xr[m]; a[2 * m] = t.x; a[2 * m + 1] = t.y; }
        ull xq[13];
#pragma unroll
        for (int l = 0; l < 13; l++) xq[l] = pack2(a[l], a[l + 7]);
        ull s[7];
#pragma unroll
        for (int u = 0; u < 7; u++) s[u] = b0d;
#pragma unroll
        for (int k = 0; k < 7; k++)
#pragma unroll
            for (int u = 0; u < 7; u++) s[u] = fma2(xq[u + k], w0d[k], s[u]);
        float m0 = -1e30f, m1 = -1e30f;
#pragma unroll
        for (int u = 0; u < 7; u++) {
            float2 v = u2f(s[u]);
            m0 = fmaxf(m0, v.x); m1 = fmaxf(m1, v.y);
        }
        m0 = fmaxf(m0, 0.f);     // P[2jp]
        m1 = fmaxf(m1, 0.f);     // P[2jp+1]
        pes[f][jp + 1] = pack2(m0, m1);     // (P[2jp], P[2jp+1]) = pe[jp+1]
        pof[f][2 * jp + 1] = m0;            // po[jp].y   = P[2jp]
        pof[f][2 * jp + 2] = m1;            // po[jp+1].x = P[2jp+1]
    }
    __syncthreads();

    // conv1 (k=5, pad 2): pure LDS.64 + FFMA2
    float b1r = b1[f];
    ull acc2[11];
#pragma unroll
    for (int j = 0; j < 11; j++) acc2[j] = pack2(b1r, b1r);

#pragma unroll 1
    for (int c = 0; c < 64; c++) {
        ull pe[13];
#pragma unroll
        for (int m = 0; m < 13; m++) pe[m] = pes[c][m];
        ull po[12];
        const ull* pou = reinterpret_cast<const ull*>(&pof[c][0]);
#pragma unroll
        for (int m = 0; m < 12; m++) po[m] = pou[m];
        const ull* wp = &d_w1u[c * 5 * 64 + f];
        ull w0u = wp[0], w1u = wp[64], w2u = wp[128], w3u = wp[192], w4u = wp[256];
#pragma unroll
        for (int j = 0; j < 11; j++) {
            acc2[j] = fma2(pe[j],     w0u, acc2[j]);
            acc2[j] = fma2(po[j],     w1u, acc2[j]);
            acc2[j] = fma2(pe[j + 1], w2u, acc2[j]);
            acc2[j] = fma2(po[j + 1], w3u, acc2[j]);
            acc2[j] = fma2(pe[j + 2], w4u, acc2[j]);
        }
    }
    float acc[22];
#pragma unroll
    for (int j = 0; j < 11; j++) {
        float2 v = u2f(acc2[j]);
        acc[2 * j] = v.x; acc[2 * j + 1] = v.y;
    }
#pragma unroll
    for (int j = 0; j < 3; j++) {
        float m = acc[7 * j];
#pragma unroll
        for (int u = 1; u < 7; u++) m = fmaxf(m, acc[7 * j + u]);
        p1s[f][j] = fmaxf(m, 0.f);
    }
    __syncthreads();

    // conv2 (k=3, len 3 -> 1)
    float s = b2[f];
#pragma unroll 1
    for (int c = 0; c < 64; c++) {
#pragma unroll
        for (int k = 0; k < 3; k++) s = fmaf(p1s[c][k], d_w2t[(c * 3 + k) * 64 + f], s);
    }
    d_H0[n * NF + f] = s;
}

// ---------------- BN1 stats ----------------
__global__ void __launch_bounds__(256) k_bns1a() {
    int t = threadIdx.x;
    int c = t & 63;
    int grp = t >> 6;
    int gid = blockIdx.x * 4 + grp;
    float s = 0.f, q = 0.f;
    for (int n = gid; n < NNODE; n += 244) {
        float v = d_H0[n * NF + c];
        s += v; q += v * v;
    }
    __shared__ float ss[256], sq[256];
    ss[t] = s; sq[t] = q;
    __syncthreads();
    if (t < 64) {
        d_bp1s[blockIdx.x * 64 + t] = ss[t] + ss[64 + t] + ss[128 + t] + ss[192 + t];
        d_bp1q[blockIdx.x * 64 + t] = sq[t] + sq[64 + t] + sq[128 + t] + sq[192 + t];
    }
}
__global__ void __launch_bounds__(64) k_bns1b(const float* __restrict__ gg,
                                              const float* __restrict__ bb) {
    int c = threadIdx.x;
    float s = 0.f, q = 0.f;
    for (int b = 0; b < 61; b++) { s += d_bp1s[b * 64 + c]; q += d_bp1q[b * 64 + c]; }
    float mean = s / (float)NNODE;
    float var = q / (float)NNODE - mean * mean;
    float rs = rsqrtf(var + 1e-5f);
    d_sc1[c] = gg[c] * rs;
    d_sh1[c] = bb[c] - mean * gg[c] * rs;
}
__global__ void __launch_bounds__(128) k_bns2b(const float* __restrict__ gg,
                                               const float* __restrict__ bb) {
    int c = threadIdx.x;
    float s = 0.f, q = 0.f;
    for (int g = 0; g < 2 * NB; g++) { s += d_bp2s[g * HC + c]; q += d_bp2q[g * HC + c]; }
    float mean = s / (float)NNODE;
    float var = q / (float)NNODE - mean * mean;
    float rs = rsqrtf(var + 1e-5f);
    d_sc2[c] = gg[c] * rs;
    d_sh2[c] = bb[c] - mean * gg[c] * rs;
}

// ---------------- GNN phase A: hw = bn?(h) @ W + b. grid (NB, 2), 128 thr ----------------
template<int K, bool BN, int INSEL, int WSEL>
__global__ void __launch_bounds__(128) k_gnn_a(const float* __restrict__ bias) {
    const float* hin = (INSEL == 0) ? (const float*)d_H0
                     : (INSEL == 1) ? (const float*)d_G1 : (const float*)d_G2;
    const ulonglong2* Wu = (WSEL == 0) ? (const ulonglong2*)d_gw0u
                         : (WSEL == 1) ? (const ulonglong2*)d_gw1u : (const ulonglong2*)d_gw2u;
    int g = blockIdx.x;
    int half = blockIdx.y;
    int n0 = half ? 31 : 0;
    int NR = half ? 30 : 31;
    int j = threadIdx.x;
    __shared__ __align__(16) float hs[31 * K];

    for (int idx = j; idx < NR * K; idx += 128) {
        float v = hin[(g * 61 + n0) * K + idx];
        if (BN) { int c = idx & (K - 1); v = fmaf(v, d_sc1[c], d_sh1[c]); }
        hs[idx] = v;
    }
    __syncthreads();

    ull acc[31];
#pragma unroll
    for (int n = 0; n < 31; n++) acc[n] = 0ull;
#pragma unroll 1
    for (int kq = 0; kq < K / 4; kq++) {
        ulonglong2 w = Wu[kq * HC + j];
#pragma unroll
        for (int n = 0; n < 31; n++) {
            ulonglong2 h2 = *reinterpret_cast<const ulonglong2*>(&hs[n * K + 4 * kq]);
            acc[n] = fma2(h2.x, w.x, acc[n]);
            acc[n] = fma2(h2.y, w.y, acc[n]);
        }
    }
    float bj = bias[j];
    for (int n = 0; n < NR; n++) {
        float2 v = u2f(acc[n]);
        d_HW[(g * 61 + n0 + n) * HC + j] = bj + v.x + v.y;
    }
}

// ---------------- GNN phase B: h' = A @ hw. grid (NB, 2), 128 thr ----------------
template<bool RELU, bool STATS, int OUTSEL>
__global__ void __launch_bounds__(128) k_gnn_b() {
    float* hout = (OUTSEL == 1) ? (float*)d_G1 : (float*)d_G2;
    int g = blockIdx.x;
    int half = blockIdx.y;
    int doff = half * 32;
    int ND = half ? 29 : 32;
    int j = threadIdx.x;
    __shared__ __align__(16) float hs[61 * HC];
    __shared__ __align__(16) float As2[61 * 36];

    for (int idx = j; idx < 61 * HC; idx += 128) hs[idx] = d_HW[g * 61 * HC + idx];
    for (int idx = j; idx < 61 * 32; idx += 128) {
        int s = idx >> 5, dd = idx & 31;
        As2[s * 36 + dd] = d_At[g * 4096 + s * 64 + doff + dd];
    }
    __syncthreads();

    ull acc[16];
#pragma unroll
    for (int p = 0; p < 16; p++) acc[p] = 0ull;
#pragma unroll 1
    for (int s = 0; s < 61; s++) {
        float v = hs[s * HC + j];
        ull v2 = pack2(v, v);
        const ulonglong2* ar = reinterpret_cast<const ulonglong2*>(&As2[s * 36]);
#pragma unroll
        for (int p = 0; p < 8; p++) {
            ulonglong2 a = ar[p];
            acc[2 * p]     = fma2(a.x, v2, acc[2 * p]);
            acc[2 * p + 1] = fma2(a.y, v2, acc[2 * p + 1]);
        }
    }
    float ssum = 0.f, sqsum = 0.f;
#pragma unroll
    for (int p = 0; p < 16; p++) {
        float2 r2 = u2f(acc[p]);
        int d0 = 2 * p, d1 = 2 * p + 1;
        if (d0 < ND) {
            float r = r2.x;
            if (STATS) { ssum += r; sqsum += r * r; }
            if (RELU) r = fmaxf(r, 0.f);
            hout[(g * 61 + doff + d0) * HC + j] = r;
        }
        if (d1 < ND) {
            float r = r2.y;
            if (STATS) { ssum += r; sqsum += r * r; }
            if (RELU) r = fmaxf(r, 0.f);
            hout[(g * 61 + doff + d1) * HC + j] = r;
        }
    }
    if (STATS) {
        d_bp2s[(g * 2 + half) * HC + j] = ssum;
        d_bp2q[(g * 2 + half) * HC + j] = sqsum;
    }
}

// ---------------- lin0: split-K over nodes. grid (61, 8), 128 thr ----------------
__global__ void __launch_bounds__(128) k_lin0(const float* __restrict__ W0) {
    int node = blockIdx.x;
    int gc = blockIdx.y;
    int j = threadIdx.x;
    __shared__ __align__(16) float vsT[HC * 20];
    float sc = d_sc2[j], sh = d_sh2[j];
#pragma unroll 1
    for (int q = 0; q < 16; q++) {
        int g = gc * 16 + q;
        vsT[j * 20 + q] = fmaf(d_G1[(g * 61 + node) * HC + j], sc, sh);
    }
    __syncthreads();
    ull acc[8];
#pragma unroll
    for (int p = 0; p < 8; p++) acc[p] = 0ull;
#pragma unroll 1
    for (int ch = 0; ch < HC; ch++) {
        float w = W0[(node * HC + ch) * HC + j];
        ull wd = pack2(w, w);
        const ulonglong2* vr = reinterpret_cast<const ulonglong2*>(&vsT[ch * 20]);
#pragma unroll
        for (int p = 0; p < 4; p++) {
            ulonglong2 v = vr[p];
            acc[2 * p]     = fma2(v.x, wd, acc[2 * p]);
            acc[2 * p + 1] = fma2(v.y, wd, acc[2 * p + 1]);
        }
    }
#pragma unroll
    for (int p = 0; p < 8; p++) {
        float2 v = u2f(acc[p]);
        int g0 = gc * 16 + 2 * p;
        d_P[(g0 * NPG + node) * HC + j] = v.x;
        d_P[((g0 + 1) * NPG + node) * HC + j] = v.y;
    }
}

// ---------------- head ----------------
__global__ void __launch_bounds__(128) k_head(const float* __restrict__ b0,
                                              const float* __restrict__ W1,
                                              const float* __restrict__ b1,
                                              const float* __restrict__ W2,
                                              const float* __restrict__ b2,
                                              float* __restrict__ out) {
    int g = blockIdx.x;
    int j = threadIdx.x;
    float z = b0[j];
    for (int node = 0; node < NPG; node++) z += d_P[(g * NPG + node) * HC + j];
    z = fmaxf(z, 0.f);
    __shared__ float z1[HC];
    z1[j] = z;
    __syncthreads();
    float a = b1[j];
    for (int k = 0; k < HC; k++) a = fmaf(z1[k], W1[k * HC + j], a);
    a = fmaxf(a, 0.f);
    __shared__ float z2[HC];
    z2[j] = a;
    __syncthreads();
    __shared__ float z3[4];
    if (j < 4) {
        float s = b2[j];
        for (int k = 0; k < HC; k++) s = fmaf(z2[k], W2[k * 4 + j], s);
        z3[j] = s;
    }
    __syncthreads();
    if (j == 0) {
        float m = fmaxf(fmaxf(z3[0], z3[1]), fmaxf(z3[2], z3[3]));
        float se = 0.f;
        for (int i = 0; i < 4; i++) se += expf(z3[i] - m);
        float l = logf(se);
        for (int i = 0; i < 4; i++) out[g * 4 + i] = z3[i] - m - l;
    }
}

// ---------------- launch ----------------
extern "C" void kernel_launch(void* const* d_in, const int* in_sizes, int n_in,
                              void* d_out, int out_size) {
    const float* x    = (const float*)d_in[0];
    const int*   ei   = (const int*)d_in[1];
    const float* ef   = (const float*)d_in[3];
    const float* cw0  = (const float*)d_in[4];
    const float* cb0  = (const float*)d_in[5];
    const float* cw1  = (const float*)d_in[6];
    const float* cb1  = (const float*)d_in[7];
    const float* cw2  = (const float*)d_in[8];
    const float* cb2  = (const float*)d_in[9];
    const float* bn1g = (const float*)d_in[10];
    const float* bn1b = (const float*)d_in[11];
    const float* gw0  = (const float*)d_in[12];
    const float* gb0  = (const float*)d_in[13];
    const float* gw1  = (const float*)d_in[14];
    const float* gb1  = (const float*)d_in[15];
    const float* gw2  = (const float*)d_in[16];
    const float* gb2  = (const float*)d_in[17];
    const float* bn2g = (const float*)d_in[18];
    const float* bn2b = (const float*)d_in[19];
    const float* lw0  = (const float*)d_in[20];
    const float* lb0  = (const float*)d_in[21];
    const float* lw1  = (const float*)d_in[22];
    const float* lb1  = (const float*)d_in[23];
    const float* lw2  = (const float*)d_in[24];
    const float* lb2  = (const float*)d_in[25];
    const float* eww  = (const float*)d_in[26];
    const float* ewb  = (const float*)d_in[27];
    float* out = (float*)d_out;

    k_prep<<<256, 256>>>(cw1, cw2, gw0, gw1, gw2);
    dim3 eg((EPG + 31) / 32, NB / 32);
    k_edges<<<eg, 1024>>>(ef, ei, eww, ewb, out);
    k_conv<<<NNODE, 64>>>(x, cw0, cb0, cb1, cb2);
    k_bns1a<<<61, 256>>>();
    k_bns1b<<<1, 64>>>(bn1g, bn1b);
    dim3 gg(NB, 2);
    k_gnn_a< 64, true,  0, 0><<<gg, 128>>>(gb0);
    k_gnn_b<true,  false, 1><<<gg, 128>>>();
    k_gnn_a<128, false, 1, 1><<<gg, 128>>>(gb1);
    k_gnn_b<true,  false, 2><<<gg, 128>>>();
    k_gnn_a<128, false, 2, 2><<<gg, 128>>>(gb2);
    k_gnn_b<false, true,  1><<<gg, 128>>>();
    k_bns2b<<<1, 128>>>(bn2g, bn2b);
    dim3 lg(NPG, 8);
    k_lin0<<<lg, 128>>>(lw0);
    k_head<<<NB, 128>>>(lb0, lw1, lb1, lw2, lb2, out);
}